// round 2
// baseline (speedup 1.0000x reference)
#include <cuda_runtime.h>
#include <math.h>

#define HW 14400
#define NB 8
#define NC 256
#define ND 64
#define BN_EPS 1e-5f

// ---------------- scratch (static device memory; no allocations) ----------------
__device__ float g_Wall[512 * 256];                 // folded weights, M padded to 512
__device__ float g_ball[512];                       // folded bias
__device__ float g_pp[(size_t)2 * NB * NC * HW];    // CBR_pp outputs, both frames (~236 MB)
__device__ float g_kb[(size_t)2 * NB * ND * HW];    // k maps
__device__ float g_vb[(size_t)2 * NB * ND * HW];    // v maps
__device__ float g_qb[(size_t)2 * NB * ND * HW];    // q maps (pre-pooling)
__device__ float g_qpool[2 * NB * 64 * ND];         // pooled q sums (scaled by 1/144 at use)
__device__ float g_pm[2 * NB * 64 * 16];            // partial row max  (15 chunks used)
__device__ float g_ps[2 * NB * 64 * 16];            // partial row sumexp
__device__ float g_mrow[2 * NB * 64];               // final row max
__device__ float g_srow[2 * NB * 64];               // final row sumexp

// ---------------- kernel 1: fold BN into conv weights ----------------
struct FoldArgs {
    const float* w[4];   // 0=pp(256 rows), 1=k, 2=v, 3=q (64 rows each)
    const float* b[4];
    const float* g[4];
    const float* bt[4];
    const float* mn[4];
    const float* vr[4];
};

__global__ void fold_kernel(FoldArgs a) {
    int m = blockIdx.x, k = threadIdx.x;
    if (m >= 448) {
        g_Wall[m * 256 + k] = 0.f;
        if (k == 0) g_ball[m] = 0.f;
        return;
    }
    int grp, i;
    if (m < 256)      { grp = 0; i = m; }
    else if (m < 320) { grp = 1; i = m - 256; }
    else if (m < 384) { grp = 2; i = m - 320; }
    else              { grp = 3; i = m - 384; }
    float sc = a.g[grp][i] * rsqrtf(a.vr[grp][i] + BN_EPS);
    g_Wall[m * 256 + k] = a.w[grp][i * 256 + k] * sc;
    if (k == 0) g_ball[m] = (a.b[grp][i] - a.mn[grp][i]) * sc + a.bt[grp][i];
}

// ---------------- kernel 2: big fused GEMM  Y[448, n] = Wall * X[:, n], relu, route ----------------
__global__ void __launch_bounds__(256) gemm_kernel(const float* __restrict__ pre,
                                                   const float* __restrict__ post) {
    __shared__ float As[8][132];   // [k][m] padded
    __shared__ float Bs[8][128];   // [k][n]
    int tid = threadIdx.x;
    int bn = blockIdx.x, bm = blockIdx.y, fb = blockIdx.z;
    int frame = fb >> 3, b = fb & 7;
    const float* X = (frame ? post : pre) + (size_t)b * NC * HW;
    int m0 = bm * 128, n0 = bn * 128;
    int tx = tid & 15, ty = tid >> 4;
    int arow = tid >> 1, acol = (tid & 1) * 4;

    float acc[8][8];
#pragma unroll
    for (int i = 0; i < 8; i++)
#pragma unroll
        for (int j = 0; j < 8; j++) acc[i][j] = 0.f;

    for (int k0 = 0; k0 < 256; k0 += 8) {
        // A tile (weights): transpose into [k][m]
        float4 a4 = *reinterpret_cast<const float4*>(&g_Wall[(m0 + arow) * 256 + k0 + acol]);
        As[acol + 0][arow] = a4.x;
        As[acol + 1][arow] = a4.y;
        As[acol + 2][arow] = a4.z;
        As[acol + 3][arow] = a4.w;
        // B tile (activations): coalesced rows of n
#pragma unroll
        for (int r = 0; r < 4; r++) {
            int idx = tid + 256 * r;
            int row = idx >> 7, col = idx & 127;
            int n = n0 + col;
            Bs[row][col] = (n < HW) ? X[(size_t)(k0 + row) * HW + n] : 0.f;
        }
        __syncthreads();
#pragma unroll
        for (int kk = 0; kk < 8; kk++) {
            float4 ra0 = *reinterpret_cast<const float4*>(&As[kk][ty * 8]);
            float4 ra1 = *reinterpret_cast<const float4*>(&As[kk][ty * 8 + 4]);
            float4 rb0 = *reinterpret_cast<const float4*>(&Bs[kk][tx * 8]);
            float4 rb1 = *reinterpret_cast<const float4*>(&Bs[kk][tx * 8 + 4]);
            float ra[8] = {ra0.x, ra0.y, ra0.z, ra0.w, ra1.x, ra1.y, ra1.z, ra1.w};
            float rb[8] = {rb0.x, rb0.y, rb0.z, rb0.w, rb1.x, rb1.y, rb1.z, rb1.w};
#pragma unroll
            for (int i = 0; i < 8; i++)
#pragma unroll
                for (int j = 0; j < 8; j++) acc[i][j] = fmaf(ra[i], rb[j], acc[i][j]);
        }
        __syncthreads();
    }

    // epilogue: bias + relu, route by channel group
    size_t fbase = (size_t)frame * NB + b;
    int nbase = n0 + tx * 8;
    bool nok = (nbase < HW);   // HW % 8 == 0: each 8-wide row is fully valid or fully out
#pragma unroll
    for (int i = 0; i < 8; i++) {
        int m = m0 + ty * 8 + i;
        if (m >= 448 || !nok) continue;
        float bias = g_ball[m];
        float* dst;
        size_t base;
        if (m < 256)      { base = (fbase * NC + m) * HW;         dst = g_pp; }
        else if (m < 320) { base = (fbase * ND + (m - 256)) * HW; dst = g_kb; }
        else if (m < 384) { base = (fbase * ND + (m - 320)) * HW; dst = g_vb; }
        else              { base = (fbase * ND + (m - 384)) * HW; dst = g_qb; }
        float y[8];
#pragma unroll
        for (int j = 0; j < 8; j++) y[j] = fmaxf(acc[i][j] + bias, 0.f);
        *reinterpret_cast<float4*>(&dst[base + nbase])     = make_float4(y[0], y[1], y[2], y[3]);
        *reinterpret_cast<float4*>(&dst[base + nbase + 4]) = make_float4(y[4], y[5], y[6], y[7]);
    }
}

// ---------------- kernel 3: deterministic pooled-query reduction ----------------
// grid (d=64, cell_row=8, frame*b=16); 96 threads = 96 central columns
__global__ void qpool_kernel() {
    __shared__ float colsum[96];
    int d = blockIdx.x, th = blockIdx.y, fb = blockIdx.z;
    int f = fb >> 3, b = fb & 7;
    const float* src = g_qb + ((size_t)(f * NB + b) * ND + d) * HW;
    int tid = threadIdx.x;          // 0..95
    int col = 12 + tid;
    int h0 = (th + 1) * 12;
    float s = 0.f;
#pragma unroll
    for (int hh = 0; hh < 12; hh++) s += src[(h0 + hh) * 120 + col];
    colsum[tid] = s;
    __syncthreads();
    if (tid < 8) {
        float t = 0.f;
#pragma unroll
        for (int j = 0; j < 12; j++) t += colsum[tid * 12 + j];
        g_qpool[((size_t)(f * NB + b) * 64 + th * 8 + tid) * ND + d] = t;  // sum; /144 at use
    }
}

// ---------------- kernel 4: chunked online softmax stats ----------------
// grid (chunk=15, b=8, dir=2); dir0: q=pre,k=post ; dir1: q=post,k=pre
__global__ void __launch_bounds__(256) stats_kernel() {
    __shared__ float ks[64][68];
    int chunk = blockIdx.x, b = blockIdx.y, dir = blockIdx.z;
    int qf = dir, kf = 1 - dir;
    int tid = threadIdx.x;
    int t = tid >> 2, sub = tid & 3;

    float qreg[64];
    const float* qp = g_qpool + ((size_t)(qf * NB + b) * 64 + t) * ND;
#pragma unroll
    for (int d2 = 0; d2 < 64; d2++) qreg[d2] = qp[d2] * (1.f / 144.f);

    const float* kbase = g_kb + (size_t)(kf * NB + b) * ND * HW;
    float m = -1e30f, s = 0.f;
    int nb0 = chunk * 960;
    for (int tile = 0; tile < 15; tile++) {
        int nt0 = nb0 + tile * 64;
#pragma unroll
        for (int r = 0; r < 16; r++) {
            int idx = tid + 256 * r;
            int d2 = idx >> 6, c = idx & 63;
            ks[d2][c] = kbase[(size_t)d2 * HW + nt0 + c];
        }
        __syncthreads();
        for (int c = sub; c < 64; c += 4) {
            float dot = 0.f;
#pragma unroll
            for (int d2 = 0; d2 < 64; d2++) dot += qreg[d2] * ks[d2][c];
            if (dot > m) { s = s * __expf(m - dot) + 1.f; m = dot; }
            else         { s += __expf(dot - m); }
        }
        __syncthreads();
    }
    // combine 4 sub-lanes (same token t occupies 4 consecutive lanes)
#pragma unroll
    for (int off = 1; off < 4; off <<= 1) {
        float om = __shfl_xor_sync(0xffffffffu, m, off);
        float os = __shfl_xor_sync(0xffffffffu, s, off);
        float M = fmaxf(m, om);
        s = s * __expf(m - M) + os * __expf(om - M);
        m = M;
    }
    if (sub == 0) {
        size_t row = (size_t)(dir * NB + b) * 64 + t;
        g_pm[row * 16 + chunk] = m;
        g_ps[row * 16 + chunk] = s;
    }
}

// ---------------- kernel 5: combine partial stats ----------------
__global__ void combine_kernel() {
    int row = threadIdx.x;   // 1024 rows
    float M = -1e30f;
#pragma unroll
    for (int c = 0; c < 15; c++) M = fmaxf(M, g_pm[row * 16 + c]);
    float S = 0.f;
#pragma unroll
    for (int c = 0; c < 15; c++) S += g_ps[row * 16 + c] * __expf(g_pm[row * 16 + c] - M);
    g_mrow[row] = M;
    g_srow[row] = S;
}

// ---------------- kernel 6: fused attn apply + diff + gate + outputs ----------------
// grid (120 n-tiles of 120 px, b=8); 256 threads; dynamic smem ~92 KB
__global__ void __launch_bounds__(256) final_kernel(const float* __restrict__ w_out,
                                                    const float* __restrict__ b_out,
                                                    float* __restrict__ out) {
    extern __shared__ float sh[];
    float* sm_m  = sh;                       // 128
    float* sm_si = sh + 128;                 // 128
    float* kt    = sh + 256;                 // 64*121
    float* bufA  = kt + 64 * 121;            // 64*121
    float* bufB  = bufA + 64 * 121;          // 64*121
    int tid = threadIdx.x;
    int n0 = blockIdx.x * 120;
    int b = blockIdx.y;

    if (tid < 128) {
        int dir = tid >> 6, t = tid & 63;
        size_t row = (size_t)(dir * NB + b) * 64 + t;
        sm_m[tid] = g_mrow[row];
        sm_si[tid] = 1.f / g_srow[row];
    }
    __syncthreads();

    int tloc = tid & 63;
    int pbase = tid >> 6;

#pragma unroll 1
    for (int dir = 0; dir < 2; dir++) {
        float* buf = dir ? bufB : bufA;
        int kf = 1 - dir, vf = dir;
        const float* kb2 = g_kb + (size_t)(kf * NB + b) * ND * HW;
        for (int e = tid; e < 64 * 120; e += 256) {
            int d2 = e / 120, p = e % 120;
            kt[d2 * 121 + p] = kb2[(size_t)d2 * HW + n0 + p];
        }
        float qreg[64];
        const float* qp = g_qpool + ((size_t)(dir * NB + b) * 64 + tloc) * ND;
#pragma unroll
        for (int d2 = 0; d2 < 64; d2++) qreg[d2] = qp[d2] * (1.f / 144.f);
        float mrow = sm_m[dir * 64 + tloc];
        float sirow = sm_si[dir * 64 + tloc];
        __syncthreads();
#pragma unroll 1
        for (int p = pbase; p < 120; p += 4) {
            float dot = 0.f;
#pragma unroll
            for (int d2 = 0; d2 < 64; d2++) dot += qreg[d2] * kt[d2 * 121 + p];
            buf[tloc * 121 + p] = __expf(dot - mrow) * sirow;
        }
        __syncthreads();
        const float* vb2 = g_vb + (size_t)(vf * NB + b) * ND * HW;
        for (int e = tid; e < 64 * 120; e += 256) {
            int d2 = e / 120, p = e % 120;
            buf[d2 * 121 + p] *= vb2[(size_t)d2 * HW + n0 + p];
        }
        __syncthreads();
    }

    // diff = |post_x - pre_x| in place in bufB
    for (int e = tid; e < 64 * 120; e += 256) {
        int d2 = e / 120, p = e % 120;
        int idx = d2 * 121 + p;
        bufB[idx] = fabsf(bufB[idx] - bufA[idx]);
    }
    __syncthreads();

    // gate + outputs, 4 channel-chunks of 64; Gs reuses kt
    float* Gs = kt;
    size_t ppBase0 = (size_t)(0 * NB + b) * NC * HW;
    size_t ppBase1 = (size_t)(1 * NB + b) * NC * HW;
    size_t outHalf = (size_t)NB * NC * HW;
#pragma unroll 1
    for (int cc = 0; cc < 4; cc++) {
        int c = cc * 64 + tloc;
        float wr[64];
#pragma unroll
        for (int d2 = 0; d2 < 64; d2++) wr[d2] = __ldg(&w_out[c * 64 + d2]);
        float bias = __ldg(&b_out[c]);
#pragma unroll 1
        for (int p = pbase; p < 120; p += 4) {
            float acc = bias;
#pragma unroll
            for (int d2 = 0; d2 < 64; d2++) acc += wr[d2] * bufB[d2 * 121 + p];
            Gs[tloc * 121 + p] = 1.f / (1.f + __expf(-acc));
        }
        __syncthreads();
        for (int e = tid; e < 64 * 120; e += 256) {
            int c2 = e / 120, p = e % 120;
            int cg = cc * 64 + c2;
            float gv = Gs[c2 * 121 + p];
            size_t off = (size_t)cg * HW + n0 + p;
            size_t oo = ((size_t)b * NC + cg) * HW + n0 + p;
            out[oo]           = g_pp[ppBase0 + off] * gv;
            out[outHalf + oo] = g_pp[ppBase1 + off] * (1.f - gv);
        }
        __syncthreads();
    }
}

// ---------------- launcher ----------------
extern "C" void kernel_launch(void* const* d_in, const int* in_sizes, int n_in,
                              void* d_out, int out_size) {
    if (n_in < 28) return;
    const float* P[28];
    for (int i = 0; i < 28; i++) P[i] = (const float*)d_in[i];

    // Resolve input ordering: dict order has w_q (16384 elems) at index 4;
    // reference-signature order has g_pp (256 elems) there.
    bool dictOrder = (in_sizes[4] == 16384);

    const float *pre = P[0], *post = P[1], *w_pp = P[2], *b_pp = P[3];
    const float *w_q, *b_q, *w_k, *b_k, *w_v, *b_v, *w_out, *b_out;
    const float *g_pp_, *bt_pp, *m_pp, *v_pp, *g_q_, *bt_q, *m_q, *v_q;
    const float *g_k_, *bt_k, *m_k, *v_k, *g_v_, *bt_v, *m_v, *v_v;
    if (dictOrder) {
        w_q = P[4];  b_q = P[5];  w_k = P[6];  b_k = P[7];
        w_v = P[8];  b_v = P[9];  w_out = P[10]; b_out = P[11];
        g_pp_ = P[12]; bt_pp = P[13]; m_pp = P[14]; v_pp = P[15];
        g_q_  = P[16]; bt_q  = P[17]; m_q  = P[18]; v_q  = P[19];
        g_k_  = P[20]; bt_k  = P[21]; m_k  = P[22]; v_k  = P[23];
        g_v_  = P[24]; bt_v  = P[25]; m_v  = P[26]; v_v  = P[27];
    } else {
        g_pp_ = P[4];  bt_pp = P[5];  m_pp = P[6];  v_pp = P[7];
        w_q = P[8];  b_q = P[9];
        g_q_ = P[10]; bt_q = P[11]; m_q = P[12]; v_q = P[13];
        w_k = P[14]; b_k = P[15];
        g_k_ = P[16]; bt_k = P[17]; m_k = P[18]; v_k = P[19];
        w_v = P[20]; b_v = P[21];
        g_v_ = P[22]; bt_v = P[23]; m_v = P[24]; v_v = P[25];
        w_out = P[26]; b_out = P[27];
    }

    FoldArgs fa;
    fa.w[0] = w_pp; fa.b[0] = b_pp; fa.g[0] = g_pp_; fa.bt[0] = bt_pp; fa.mn[0] = m_pp; fa.vr[0] = v_pp;
    fa.w[1] = w_k;  fa.b[1] = b_k;  fa.g[1] = g_k_;  fa.bt[1] = bt_k;  fa.mn[1] = m_k;  fa.vr[1] = v_k;
    fa.w[2] = w_v;  fa.b[2] = b_v;  fa.g[2] = g_v_;  fa.bt[2] = bt_v;  fa.mn[2] = m_v;  fa.vr[2] = v_v;
    fa.w[3] = w_q;  fa.b[3] = b_q;  fa.g[3] = g_q_;  fa.bt[3] = bt_q;  fa.mn[3] = m_q;  fa.vr[3] = v_q;

    static bool attr_done = false;
    const int FINAL_SMEM = (256 + 3 * 64 * 121) * 4;   // 93,952 bytes
    if (!attr_done) {
        cudaFuncSetAttribute(final_kernel, cudaFuncAttributeMaxDynamicSharedMemorySize, FINAL_SMEM);
        attr_done = true;
    }

    fold_kernel<<<512, 256>>>(fa);
    gemm_kernel<<<dim3(113, 4, 16), 256>>>(pre, post);
    qpool_kernel<<<dim3(64, 8, 16), 96>>>();
    stats_kernel<<<dim3(15, 8, 2), 256>>>();
    combine_kernel<<<1, 1024>>>();
    final_kernel<<<dim3(120, 8), 256, FINAL_SMEM>>>(w_out, b_out, (float*)d_out);
}

// round 6
// speedup vs baseline: 1.5480x; 1.5480x over previous
// tf32 tensor-core pipeline, v2: adds missing <stdint.h> (R5 compile failure root cause).
#include <cuda_runtime.h>
#include <stdint.h>
#include <math.h>

#define HW 14400
#define NB 8
#define NC 256
#define ND 64
#define BN_EPS 1e-5f
#define SCHUNKS 45   /* softmax stat chunks: 45 * 320 px */

// ---------------- scratch (static device memory; no allocations) ----------------
__device__ float g_Wall[512 * 256];                 // folded weights, M padded to 512
__device__ float g_ball[512];                       // folded bias
__device__ float g_pp[(size_t)2 * NB * NC * HW];    // CBR_pp outputs, both frames
__device__ float g_kb[(size_t)2 * NB * ND * HW];    // k maps
__device__ float g_vb[(size_t)2 * NB * ND * HW];    // v maps
__device__ float g_qb[(size_t)2 * NB * ND * HW];    // q maps (pre-pooling)
__device__ float g_qpool[2 * NB * 64 * ND];         // pooled q sums (scaled by 1/144 at use)
__device__ float g_pm[2 * NB * 64 * 48];            // partial row max
__device__ float g_ps[2 * NB * 64 * 48];            // partial row sumexp
__device__ float g_mrow[2 * NB * 64];               // final row max
__device__ float g_srow[2 * NB * 64];               // final row sumexp

// ---------------- helpers ----------------
__device__ __forceinline__ uint32_t f2tf32(float x) {
    uint32_t u;
    asm("cvt.rna.tf32.f32 %0, %1;" : "=r"(u) : "f"(x));
    return u;
}

__device__ __forceinline__ void mma_tf32(float* c, const uint32_t* a, const uint32_t* b) {
    asm volatile(
        "mma.sync.aligned.m16n8k8.row.col.f32.tf32.tf32.f32 "
        "{%0,%1,%2,%3}, {%4,%5,%6,%7}, {%8,%9}, {%0,%1,%2,%3};"
        : "+f"(c[0]), "+f"(c[1]), "+f"(c[2]), "+f"(c[3])
        : "r"(a[0]), "r"(a[1]), "r"(a[2]), "r"(a[3]), "r"(b[0]), "r"(b[1]));
}

// ---------------- kernel 1: fold BN into conv weights ----------------
struct FoldArgs {
    const float* w[4];   // 0=pp(256 rows), 1=k, 2=v, 3=q (64 rows each)
    const float* b[4];
    const float* g[4];
    const float* bt[4];
    const float* mn[4];
    const float* vr[4];
};

__global__ void fold_kernel(FoldArgs a) {
    int m = blockIdx.x, k = threadIdx.x;
    if (m >= 448) {
        g_Wall[m * 256 + k] = 0.f;
        if (k == 0) g_ball[m] = 0.f;
        return;
    }
    int grp, i;
    if (m < 256)      { grp = 0; i = m; }
    else if (m < 320) { grp = 1; i = m - 256; }
    else if (m < 384) { grp = 2; i = m - 320; }
    else              { grp = 3; i = m - 384; }
    float sc = a.g[grp][i] * rsqrtf(a.vr[grp][i] + BN_EPS);
    g_Wall[m * 256 + k] = a.w[grp][i * 256 + k] * sc;
    if (k == 0) g_ball[m] = (a.b[grp][i] - a.mn[grp][i]) * sc + a.bt[grp][i];
}

// ---------------- kernel 2: tensor-core GEMM  Y[512, n] = Wall * X[:, n], relu, route ----------------
// Block tile M=128 N=128 K=256, 8 warps (2m x 4n), warp tile 64x32, mma m16n8k8 tf32.
// Smem layouts chosen conflict-free for fragment loads:
//   As[m][k]  stride 36 : addr%32 = g*4 + tg  (distinct across warp)
//   Bs[k][n]  stride 136: addr%32 = tg*8 + g  (distinct across warp)
__global__ void __launch_bounds__(256) gemm_tc(const float* __restrict__ pre,
                                               const float* __restrict__ post) {
    __shared__ uint32_t As[128][36];
    __shared__ uint32_t Bs[32][136];
    int tid = threadIdx.x;
    int lane = tid & 31, warp = tid >> 5;
    int wm = warp & 1, wn = warp >> 1;          // 2 x 4 warp grid
    int bn = blockIdx.x, bm = blockIdx.y, fb = blockIdx.z;
    int frame = fb >> 3, b = fb & 7;
    const float* X = (frame ? post : pre) + (size_t)b * NC * HW;
    int m0 = bm * 128, n0 = bn * 128;
    int g = lane >> 2, tg = lane & 3;

    float acc[4][4][4];
#pragma unroll
    for (int i = 0; i < 4; i++)
#pragma unroll
        for (int j = 0; j < 4; j++)
#pragma unroll
            for (int r = 0; r < 4; r++) acc[i][j][r] = 0.f;

    for (int kc = 0; kc < 256; kc += 32) {
        // A tile: 128 x 32 from g_Wall[m][k] (row-major) -> As[m][k]
#pragma unroll
        for (int r = 0; r < 4; r++) {
            int pos = tid + 256 * r;            // 1024 float4 slots
            int m = pos >> 3, kq = pos & 7;
            float4 a4 = *reinterpret_cast<const float4*>(&g_Wall[(m0 + m) * 256 + kc + kq * 4]);
            As[m][kq * 4 + 0] = f2tf32(a4.x);
            As[m][kq * 4 + 1] = f2tf32(a4.y);
            As[m][kq * 4 + 2] = f2tf32(a4.z);
            As[m][kq * 4 + 3] = f2tf32(a4.w);
        }
        // B tile: 32 x 128 from X[k][n] -> Bs[k][n]
#pragma unroll
        for (int r = 0; r < 4; r++) {
            int pos = tid + 256 * r;
            int kr = pos >> 5, nq = pos & 31;
            int n = n0 + nq * 4;
            float4 b4 = (n < HW)
                ? *reinterpret_cast<const float4*>(&X[(size_t)(kc + kr) * HW + n])
                : make_float4(0.f, 0.f, 0.f, 0.f);
            Bs[kr][nq * 4 + 0] = f2tf32(b4.x);
            Bs[kr][nq * 4 + 1] = f2tf32(b4.y);
            Bs[kr][nq * 4 + 2] = f2tf32(b4.z);
            Bs[kr][nq * 4 + 3] = f2tf32(b4.w);
        }
        __syncthreads();
#pragma unroll
        for (int ks = 0; ks < 4; ks++) {
            int k8 = ks * 8;
            uint32_t afr[4][4], bfr[4][2];
#pragma unroll
            for (int mf = 0; mf < 4; mf++) {
                int mr = wm * 64 + mf * 16 + g;
                afr[mf][0] = As[mr][k8 + tg];
                afr[mf][1] = As[mr + 8][k8 + tg];
                afr[mf][2] = As[mr][k8 + tg + 4];
                afr[mf][3] = As[mr + 8][k8 + tg + 4];
            }
#pragma unroll
            for (int nf = 0; nf < 4; nf++) {
                int nc2 = wn * 32 + nf * 8 + g;
                bfr[nf][0] = Bs[k8 + tg][nc2];
                bfr[nf][1] = Bs[k8 + tg + 4][nc2];
            }
#pragma unroll
            for (int mf = 0; mf < 4; mf++)
#pragma unroll
                for (int nf = 0; nf < 4; nf++)
                    mma_tf32(acc[mf][nf], afr[mf], bfr[nf]);
        }
        __syncthreads();
    }

    // epilogue: bias + relu, route by channel group
    size_t fbase = (size_t)frame * NB + b;
#pragma unroll
    for (int mf = 0; mf < 4; mf++) {
#pragma unroll
        for (int half = 0; half < 2; half++) {
            int m = m0 + wm * 64 + mf * 16 + g + half * 8;
            if (m >= 448) continue;
            float bias = g_ball[m];
            float* dst;
            size_t base;
            if (m < 256)      { base = (fbase * NC + m) * HW;         dst = g_pp; }
            else if (m < 320) { base = (fbase * ND + (m - 256)) * HW; dst = g_kb; }
            else if (m < 384) { base = (fbase * ND + (m - 320)) * HW; dst = g_vb; }
            else              { base = (fbase * ND + (m - 384)) * HW; dst = g_qb; }
#pragma unroll
            for (int nf = 0; nf < 4; nf++) {
                int n = n0 + wn * 32 + nf * 8 + tg * 2;
                if (n < HW) {
                    float v0 = fmaxf(acc[mf][nf][half * 2 + 0] + bias, 0.f);
                    float v1 = fmaxf(acc[mf][nf][half * 2 + 1] + bias, 0.f);
                    *reinterpret_cast<float2*>(&dst[base + n]) = make_float2(v0, v1);
                }
            }
        }
    }
}

// ---------------- kernel 3: deterministic pooled-query reduction ----------------
// grid (d=64, cell_row=8, frame*b=16); 96 threads = 96 central columns
__global__ void qpool_kernel() {
    __shared__ float colsum[96];
    int d = blockIdx.x, th = blockIdx.y, fb = blockIdx.z;
    int f = fb >> 3, b = fb & 7;
    const float* src = g_qb + ((size_t)(f * NB + b) * ND + d) * HW;
    int tid = threadIdx.x;          // 0..95
    int col = 12 + tid;
    int h0 = (th + 1) * 12;
    float s = 0.f;
#pragma unroll
    for (int hh = 0; hh < 12; hh++) s += src[(h0 + hh) * 120 + col];
    colsum[tid] = s;
    __syncthreads();
    if (tid < 8) {
        float t = 0.f;
#pragma unroll
        for (int j = 0; j < 12; j++) t += colsum[tid * 12 + j];
        g_qpool[((size_t)(f * NB + b) * 64 + th * 8 + tid) * ND + d] = t;  // sum; /144 at use
    }
}

// ---------------- kernel 4: chunked online softmax stats ----------------
// grid (chunk=45, b=8, dir=2); each chunk covers 5 tiles of 64 px = 320 px
__global__ void __launch_bounds__(256) stats_kernel() {
    __shared__ float ks[64][68];
    int chunk = blockIdx.x, b = blockIdx.y, dir = blockIdx.z;
    int qf = dir, kf = 1 - dir;
    int tid = threadIdx.x;
    int t = tid >> 2, sub = tid & 3;

    float qreg[64];
    const float* qp = g_qpool + ((size_t)(qf * NB + b) * 64 + t) * ND;
#pragma unroll
    for (int d2 = 0; d2 < 64; d2++) qreg[d2] = qp[d2] * (1.f / 144.f);

    const float* kbase = g_kb + (size_t)(kf * NB + b) * ND * HW;
    float m = -1e30f, s = 0.f;
    int nb0 = chunk * 320;
    for (int tile = 0; tile < 5; tile++) {
        int nt0 = nb0 + tile * 64;
#pragma unroll
        for (int r = 0; r < 16; r++) {
            int idx = tid + 256 * r;
            int d2 = idx >> 6, c = idx & 63;
            ks[d2][c] = kbase[(size_t)d2 * HW + nt0 + c];
        }
        __syncthreads();
        for (int c = sub; c < 64; c += 4) {
            float dot = 0.f;
#pragma unroll
            for (int d2 = 0; d2 < 64; d2++) dot += qreg[d2] * ks[d2][c];
            if (dot > m) { s = s * __expf(m - dot) + 1.f; m = dot; }
            else         { s += __expf(dot - m); }
        }
        __syncthreads();
    }
    // combine 4 sub-lanes (same token t occupies 4 consecutive lanes)
#pragma unroll
    for (int off = 1; off < 4; off <<= 1) {
        float om = __shfl_xor_sync(0xffffffffu, m, off);
        float os = __shfl_xor_sync(0xffffffffu, s, off);
        float M = fmaxf(m, om);
        s = s * __expf(m - M) + os * __expf(om - M);
        m = M;
    }
    if (sub == 0) {
        size_t row = (size_t)(dir * NB + b) * 64 + t;
        g_pm[row * 48 + chunk] = m;
        g_ps[row * 48 + chunk] = s;
    }
}

// ---------------- kernel 5: combine partial stats ----------------
__global__ void combine_kernel() {
    int row = threadIdx.x;   // 1024 rows
    float M = -1e30f;
#pragma unroll
    for (int c = 0; c < SCHUNKS; c++) M = fmaxf(M, g_pm[row * 48 + c]);
    float S = 0.f;
#pragma unroll
    for (int c = 0; c < SCHUNKS; c++) S += g_ps[row * 48 + c] * __expf(g_pm[row * 48 + c] - M);
    g_mrow[row] = M;
    g_srow[row] = S;
}

// ---------------- kernel 6: fused attn apply + diff + gate + outputs ----------------
// grid (120 n-tiles of 120 px, b=8); 256 threads; dynamic smem ~92 KB
__global__ void __launch_bounds__(256) final_kernel(const float* __restrict__ w_out,
                                                    const float* __restrict__ b_out,
                                                    float* __restrict__ out) {
    extern __shared__ float sh[];
    float* sm_m  = sh;                       // 128
    float* sm_si = sh + 128;                 // 128
    float* kt    = sh + 256;                 // 64*121
    float* bufA  = kt + 64 * 121;            // 64*121
    float* bufB  = bufA + 64 * 121;          // 64*121
    int tid = threadIdx.x;
    int n0 = blockIdx.x * 120;
    int b = blockIdx.y;

    if (tid < 128) {
        int dir = tid >> 6, t = tid & 63;
        size_t row = (size_t)(dir * NB + b) * 64 + t;
        sm_m[tid] = g_mrow[row];
        sm_si[tid] = 1.f / g_srow[row];
    }
    __syncthreads();

    int tloc = tid & 63;
    int pbase = tid >> 6;

#pragma unroll 1
    for (int dir = 0; dir < 2; dir++) {
        float* buf = dir ? bufB : bufA;
        int kf = 1 - dir, vf = dir;
        const float* kb2 = g_kb + (size_t)(kf * NB + b) * ND * HW;
        for (int e = tid; e < 64 * 120; e += 256) {
            int d2 = e / 120, p = e % 120;
            kt[d2 * 121 + p] = kb2[(size_t)d2 * HW + n0 + p];
        }
        float qreg[64];
        const float* qp = g_qpool + ((size_t)(dir * NB + b) * 64 + tloc) * ND;
#pragma unroll
        for (int d2 = 0; d2 < 64; d2++) qreg[d2] = qp[d2] * (1.f / 144.f);
        float mrow = sm_m[dir * 64 + tloc];
        float sirow = sm_si[dir * 64 + tloc];
        __syncthreads();
#pragma unroll 1
        for (int p = pbase; p < 120; p += 4) {
            float dot = 0.f;
#pragma unroll
            for (int d2 = 0; d2 < 64; d2++) dot += qreg[d2] * kt[d2 * 121 + p];
            buf[tloc * 121 + p] = __expf(dot - mrow) * sirow;
        }
        __syncthreads();
        const float* vb2 = g_vb + (size_t)(vf * NB + b) * ND * HW;
        for (int e = tid; e < 64 * 120; e += 256) {
            int d2 = e / 120, p = e % 120;
            buf[d2 * 121 + p] *= vb2[(size_t)d2 * HW + n0 + p];
        }
        __syncthreads();
    }

    // diff = |post_x - pre_x| in place in bufB
    for (int e = tid; e < 64 * 120; e += 256) {
        int d2 = e / 120, p = e % 120;
        int idx = d2 * 121 + p;
        bufB[idx] = fabsf(bufB[idx] - bufA[idx]);
    }
    __syncthreads();

    // gate + outputs, 4 channel-chunks of 64; Gs reuses kt
    float* Gs = kt;
    size_t ppBase0 = (size_t)(0 * NB + b) * NC * HW;
    size_t ppBase1 = (size_t)(1 * NB + b) * NC * HW;
    size_t outHalf = (size_t)NB * NC * HW;
#pragma unroll 1
    for (int cc = 0; cc < 4; cc++) {
        int c = cc * 64 + tloc;
        float wr[64];
#pragma unroll
        for (int d2 = 0; d2 < 64; d2++) wr[d2] = __ldg(&w_out[c * 64 + d2]);
        float bias = __ldg(&b_out[c]);
#pragma unroll 1
        for (int p = pbase; p < 120; p += 4) {
            float acc = bias;
#pragma unroll
            for (int d2 = 0; d2 < 64; d2++) acc += wr[d2] * bufB[d2 * 121 + p];
            Gs[tloc * 121 + p] = 1.f / (1.f + __expf(-acc));
        }
        __syncthreads();
        for (int e = tid; e < 64 * 120; e += 256) {
            int c2 = e / 120, p = e % 120;
            int cg = cc * 64 + c2;
            float gv = Gs[c2 * 121 + p];
            size_t off = (size_t)cg * HW + n0 + p;
            size_t oo = ((size_t)b * NC + cg) * HW + n0 + p;
            out[oo]           = g_pp[ppBase0 + off] * gv;
            out[outHalf + oo] = g_pp[ppBase1 + off] * (1.f - gv);
        }
        __syncthreads();
    }
}

// ---------------- launcher ----------------
extern "C" void kernel_launch(void* const* d_in, const int* in_sizes, int n_in,
                              void* d_out, int out_size) {
    if (n_in < 28) return;
    const float* P[28];
    for (int i = 0; i < 28; i++) P[i] = (const float*)d_in[i];

    // Resolve input ordering: dict order has w_q (16384 elems) at index 4;
    // reference-signature order has g_pp (256 elems) there.
    bool dictOrder = (in_sizes[4] == 16384);

    const float *pre = P[0], *post = P[1], *w_pp = P[2], *b_pp = P[3];
    const float *w_q, *b_q, *w_k, *b_k, *w_v, *b_v, *w_out, *b_out;
    const float *g_pp_, *bt_pp, *m_pp, *v_pp, *g_q_, *bt_q, *m_q, *v_q;
    const float *g_k_, *bt_k, *m_k, *v_k, *g_v_, *bt_v, *m_v, *v_v;
    if (dictOrder) {
        w_q = P[4];  b_q = P[5];  w_k = P[6];  b_k = P[7];
        w_v = P[8];  b_v = P[9];  w_out = P[10]; b_out = P[11];
        g_pp_ = P[12]; bt_pp = P[13]; m_pp = P[14]; v_pp = P[15];
        g_q_  = P[16]; bt_q  = P[17]; m_q  = P[18]; v_q  = P[19];
        g_k_  = P[20]; bt_k  = P[21]; m_k  = P[22]; v_k  = P[23];
        g_v_  = P[24]; bt_v  = P[25]; m_v  = P[26]; v_v  = P[27];
    } else {
        g_pp_ = P[4];  bt_pp = P[5];  m_pp = P[6];  v_pp = P[7];
        w_q = P[8];  b_q = P[9];
        g_q_ = P[10]; bt_q = P[11]; m_q = P[12]; v_q = P[13];
        w_k = P[14]; b_k = P[15];
        g_k_ = P[16]; bt_k = P[17]; m_k = P[18]; v_k = P[19];
        w_v = P[20]; b_v = P[21];
        g_v_ = P[22]; bt_v = P[23]; m_v = P[24]; v_v = P[25];
        w_out = P[26]; b_out = P[27];
    }

    FoldArgs fa;
    fa.w[0] = w_pp; fa.b[0] = b_pp; fa.g[0] = g_pp_; fa.bt[0] = bt_pp; fa.mn[0] = m_pp; fa.vr[0] = v_pp;
    fa.w[1] = w_k;  fa.b[1] = b_k;  fa.g[1] = g_k_;  fa.bt[1] = bt_k;  fa.mn[1] = m_k;  fa.vr[1] = v_k;
    fa.w[2] = w_v;  fa.b[2] = b_v;  fa.g[2] = g_v_;  fa.bt[2] = bt_v;  fa.mn[2] = m_v;  fa.vr[2] = v_v;
    fa.w[3] = w_q;  fa.b[3] = b_q;  fa.g[3] = g_q_;  fa.bt[3] = bt_q;  fa.mn[3] = m_q;  fa.vr[3] = v_q;

    static bool attr_done = false;
    const int FINAL_SMEM = (256 + 3 * 64 * 121) * 4;   // 93,952 bytes
    if (!attr_done) {
        cudaFuncSetAttribute(final_kernel, cudaFuncAttributeMaxDynamicSharedMemorySize, FINAL_SMEM);
        attr_done = true;
    }

    fold_kernel<<<512, 256>>>(fa);
    gemm_tc<<<dim3(113, 4, 16), 256>>>(pre, post);
    qpool_kernel<<<dim3(64, 8, 16), 96>>>();
    stats_kernel<<<dim3(SCHUNKS, 8, 2), 256>>>();
    combine_kernel<<<1, 1024>>>();
    final_kernel<<<dim3(120, 8), 256, FINAL_SMEM>>>(w_out, b_out, (float*)d_out);
}